// round 2
// baseline (speedup 1.0000x reference)
#include <cuda_runtime.h>

#define NN 100000
#define NE 3200000
#define DIMK 256
#define NC 32
#define NG 64

// Scratch (device globals; no allocation allowed)
__device__ float g_deg[NN];
__device__ float g_dinv[NN];
__device__ float g_hs[(size_t)NN * NC];   // h * dinv[row]  (gathered by edges)
__device__ float g_agg[(size_t)NN * NC];  // per-node aggregation accumulator
__device__ float g_pool[NG * NC];
__device__ float g_cnt[NG];

// ---------------------------------------------------------------- init
__global__ void k_init() {
    int i = blockIdx.x * blockDim.x + threadIdx.x;
    if (i < NN) g_deg[i] = 1.0f;           // self-loop contributes 1
    if (i < NG * NC) g_pool[i] = 0.0f;
    if (i < NG) g_cnt[i] = 0.0f;
}

// ---------------------------------------------------------------- degree
__global__ void k_deg(const int* __restrict__ dst) {
    int i = blockIdx.x * blockDim.x + threadIdx.x;
    if (i < NE) atomicAdd(&g_deg[dst[i]], 1.0f);
}

__global__ void k_dinv() {
    int i = blockIdx.x * blockDim.x + threadIdx.x;
    if (i < NN) g_dinv[i] = rsqrtf(g_deg[i]);
}

// ---------------------------------------------------------------- GEMM + self term
// h[row,:] = x[row,:] @ W ;  g_hs = h*dinv ;  g_agg init = h*dinv^2 (self loop)
__global__ void __launch_bounds__(256) k_gemm(const float* __restrict__ x,
                                              const float* __restrict__ W) {
    __shared__ float Wt[NC * (DIMK + 4)];   // transposed W [c][k], stride 260 (pad)
    __shared__ float xs[8][DIMK];           // one staged row per warp

    int tid = threadIdx.x;
    // Load + transpose W (row-major [256][32]) into Wt[c][k]
    for (int i = tid; i < DIMK * NC; i += 256) {
        int k = i >> 5, c = i & 31;
        Wt[c * (DIMK + 4) + k] = W[i];
    }
    __syncthreads();

    int warp = tid >> 5, lane = tid & 31;
    int row = blockIdx.x * 8 + warp;
    if (row >= NN) return;

    // Stage x row (256 floats) via 2 float4 loads per lane
    const float4* xr = (const float4*)(x + (size_t)row * DIMK);
    ((float4*)&xs[warp][0])[lane]   = xr[lane];
    ((float4*)&xs[warp][128])[lane] = xr[lane + 32];
    __syncwarp();

    float acc = 0.0f;
    const float4* wt4 = (const float4*)&Wt[lane * (DIMK + 4)];
    const float4* xs4 = (const float4*)&xs[warp][0];
#pragma unroll
    for (int kq = 0; kq < DIMK / 4; kq++) {
        float4 xv = xs4[kq];   // broadcast, conflict-free
        float4 wv = wt4[kq];   // padded stride -> conflict-free
        acc = fmaf(xv.x, wv.x, acc);
        acc = fmaf(xv.y, wv.y, acc);
        acc = fmaf(xv.z, wv.z, acc);
        acc = fmaf(xv.w, wv.w, acc);
    }

    float di = g_dinv[row];
    float hsv = acc * di;
    g_hs[(size_t)row * NC + lane]  = hsv;
    g_agg[(size_t)row * NC + lane] = hsv * di;   // self-loop: dinv^2 * h
}

// ---------------------------------------------------------------- edge scatter
// One warp handles 32 edges: coalesced metadata load, then per edge:
// lane c gathers hs[src*32+c] (one 128B line) and RED.ADDs into agg[dst*32+c].
__global__ void __launch_bounds__(256) k_scatter(const int* __restrict__ src,
                                                 const int* __restrict__ dst) {
    int gw = (blockIdx.x * blockDim.x + threadIdx.x) >> 5;
    int lane = threadIdx.x & 31;
    int base = gw * 32;
    if (base >= NE) return;

    int e = base + lane;
    int s = 0, d = 0;
    float w = 0.0f;
    if (e < NE) {
        s = src[e];
        d = dst[e];
        w = g_dinv[d];
    }
    int cnt = min(32, NE - base);
#pragma unroll 4
    for (int j = 0; j < cnt; j++) {
        int   sj = __shfl_sync(0xffffffffu, s, j);
        int   dj = __shfl_sync(0xffffffffu, d, j);
        float wj = __shfl_sync(0xffffffffu, w, j);
        float v = g_hs[(size_t)sj * NC + lane] * wj;
        atomicAdd(&g_agg[(size_t)dj * NC + lane], v);
    }
}

// ---------------------------------------------------------------- pooling
// batch is sorted: each warp owns a contiguous node range and accumulates in
// registers, flushing to smem only at graph boundaries (~64 total).
__global__ void __launch_bounds__(256) k_pool(const int* __restrict__ batch) {
    __shared__ float sp[NG * NC];
    __shared__ float sc[NG];
    int tid = threadIdx.x;
    for (int i = tid; i < NG * NC; i += 256) sp[i] = 0.0f;
    if (tid < NG) sc[tid] = 0.0f;
    __syncthreads();

    int warp = tid >> 5, lane = tid & 31;
    int wid = blockIdx.x * 8 + warp;
    int nwarps = gridDim.x * 8;
    int per = (NN + nwarps - 1) / nwarps;
    int s0 = wid * per;
    int s1 = min(NN, s0 + per);

    float acc = 0.0f, cacc = 0.0f;
    int curg = -1;
    for (int i = s0; i < s1; i++) {
        int g = __ldg(&batch[i]);          // uniform broadcast load
        if (g != curg) {
            if (curg >= 0) {
                atomicAdd(&sp[curg * NC + lane], acc);
                if (lane == 0) atomicAdd(&sc[curg], cacc);
            }
            curg = g; acc = 0.0f; cacc = 0.0f;
        }
        acc  += g_agg[(size_t)i * NC + lane];
        cacc += 1.0f;
    }
    if (curg >= 0) {
        atomicAdd(&sp[curg * NC + lane], acc);
        if (lane == 0) atomicAdd(&sc[curg], cacc);
    }
    __syncthreads();

    for (int i = tid; i < NG * NC; i += 256) atomicAdd(&g_pool[i], sp[i]);
    if (tid < NG) atomicAdd(&g_cnt[tid], sc[tid]);
}

// ---------------------------------------------------------------- finalize
__global__ void k_final(const float* __restrict__ b, float* __restrict__ out) {
    int i = blockIdx.x * blockDim.x + threadIdx.x;
    if (i < NG * NC) {
        int g = i >> 5, c = i & 31;
        float cnt = g_cnt[g];
        out[i] = (cnt > 0.0f) ? (g_pool[i] / cnt + b[c]) : 0.0f;
    }
}

// ---------------------------------------------------------------- launch
extern "C" void kernel_launch(void* const* d_in, const int* in_sizes, int n_in,
                              void* d_out, int out_size) {
    const float* x     = (const float*)d_in[0];
    const float* W     = (const float*)d_in[1];
    const float* b     = (const float*)d_in[2];
    const int*   ei    = (const int*)d_in[3];
    const int*   batch = (const int*)d_in[4];
    float*       out   = (float*)d_out;

    const int* src = ei;        // edge_index[0]
    const int* dst = ei + NE;   // edge_index[1]

    k_init<<<(NN + 255) / 256, 256>>>();
    k_deg<<<(NE + 255) / 256, 256>>>(dst);
    k_dinv<<<(NN + 255) / 256, 256>>>();
    k_gemm<<<(NN + 7) / 8, 256>>>(x, W);
    k_scatter<<<(NE / 32 + 7) / 8, 256>>>(src, dst);   // one warp per 32 edges
    k_pool<<<64, 256>>>(batch);
    k_final<<<(NG * NC + 255) / 256, 256>>>(b, out);
}

// round 3
// speedup vs baseline: 1.5730x; 1.5730x over previous
#include <cuda_runtime.h>
#include <cuda_fp16.h>

#define NN 100000
#define NE 3200000
#define DIMK 256
#define NC 32
#define NG 64
#define RB 8     // rows per warp in gemm
#define KC 32    // k-chunk in gemm

// Scratch (device globals; no allocation allowed)
__device__ float  g_deg[NN];
__device__ float  g_dinv[NN];
__device__ __half g_hs_h[(size_t)NN * NC];  // h * dinv[row] in fp16 (edge gather payload)
__device__ float  g_agg[(size_t)NN * NC];   // unweighted sum of hs over in-edges (+ self hs)
__device__ float  g_pool[NG * NC];
__device__ float  g_cnt[NG];

// ---------------------------------------------------------------- init
__global__ void k_init() {
    int i = blockIdx.x * blockDim.x + threadIdx.x;
    if (i < NN) g_deg[i] = 1.0f;           // self-loop contributes 1
    if (i < NG * NC) g_pool[i] = 0.0f;
    if (i < NG) g_cnt[i] = 0.0f;
}

// ---------------------------------------------------------------- degree
__global__ void k_deg(const int* __restrict__ dst) {
    int i = blockIdx.x * blockDim.x + threadIdx.x;
    if (i < NE) atomicAdd(&g_deg[dst[i]], 1.0f);
}

__global__ void k_dinv() {
    int i = blockIdx.x * blockDim.x + threadIdx.x;
    if (i < NN) g_dinv[i] = rsqrtf(g_deg[i]);
}

// ---------------------------------------------------------------- GEMM + self term
// h[row,:] = x[row,:] @ W ; hs = h*dinv ; g_hs_h = half(hs) ; g_agg init = hs.
// FFMA-bound design: warp owns column c=lane; W k-chunk cached in 32 regs
// (amortized over RB rows); x read via broadcast LDS (1 wavefront).
__global__ void __launch_bounds__(256) k_gemm(const float* __restrict__ x,
                                              const float* __restrict__ W) {
    __shared__ float Wt[NC][DIMK + 4];     // transposed W [c][k]
    __shared__ float xs[8][RB][KC];        // per-warp x staging for current k-chunk

    int tid = threadIdx.x, warp = tid >> 5, lane = tid & 31;

    // One-time: transpose W (row-major [256][32]) into Wt[c][k]
    for (int i = tid; i < DIMK * NC; i += 256) {
        int k = i >> 5, c = i & 31;
        Wt[c][k] = W[i];
    }
    __syncthreads();

    int row0 = blockIdx.x * (8 * RB) + warp * RB;

    float acc[RB];
#pragma unroll
    for (int r = 0; r < RB; r++) acc[r] = 0.0f;

#pragma unroll
    for (int kc = 0; kc < DIMK; kc += KC) {
        // Cache W chunk for this lane's column in registers (8 LDS.128)
        float4 wr[KC / 4];
#pragma unroll
        for (int q = 0; q < KC / 4; q++)
            wr[q] = *(const float4*)&Wt[lane][kc + 4 * q];

        __syncwarp();   // xs reuse across k-chunks
        // Stage x chunk for RB rows: 64 float4 = 2 per lane, coalesced 128B/row
#pragma unroll
        for (int it = 0; it < 2; it++) {
            int idx = it * 32 + lane;          // 0..63
            int r   = idx >> 3;                // row 0..7
            int q   = idx & 7;                 // float4 within chunk
            int row = row0 + r;
            int rowc = row < NN ? row : NN - 1;
            float4 v = *(const float4*)&x[(size_t)rowc * DIMK + kc + 4 * q];
            *(float4*)&xs[warp][r][4 * q] = v;
        }
        __syncwarp();

#pragma unroll
        for (int r = 0; r < RB; r++) {
#pragma unroll
            for (int q = 0; q < KC / 4; q++) {
                float4 xv = *(const float4*)&xs[warp][r][4 * q];  // broadcast
                acc[r] = fmaf(xv.x, wr[q].x, acc[r]);
                acc[r] = fmaf(xv.y, wr[q].y, acc[r]);
                acc[r] = fmaf(xv.z, wr[q].z, acc[r]);
                acc[r] = fmaf(xv.w, wr[q].w, acc[r]);
            }
        }
    }

#pragma unroll
    for (int r = 0; r < RB; r++) {
        int row = row0 + r;
        if (row < NN) {
            float hsv = acc[r] * g_dinv[row];
            g_hs_h[(size_t)row * NC + lane] = __float2half(hsv);
            g_agg[(size_t)row * NC + lane] = hsv;   // self-loop term (unweighted hs)
        }
    }
}

// ---------------------------------------------------------------- edge scatter
// out[dst] = dinv[dst] * sum(hs[src]) -> dinv folded into pool pass.
// Warp handles 32 edges; 2 edges per iteration (16 lanes each), half2 gather
// (64B/edge), f32 v2 reduction into g_agg (128B/edge).
__global__ void __launch_bounds__(256) k_scatter(const int* __restrict__ src,
                                                 const int* __restrict__ dst) {
    int gw = (blockIdx.x * blockDim.x + threadIdx.x) >> 5;
    int lane = threadIdx.x & 31;
    int base = gw * 32;
    if (base >= NE) return;

    int e = base + lane;
    int s = 0, d = 0;
    if (e < NE) { s = src[e]; d = dst[e]; }
    int cnt = min(32, NE - base);

    int g   = lane >> 4;      // which edge of the pair
    int l16 = lane & 15;      // 16 lanes cover 32 channels via half2
    const half2* hs2 = (const half2*)g_hs_h;

#pragma unroll 4
    for (int j = 0; j < 16; j++) {
        int jj = 2 * j + g;
        int   sj = __shfl_sync(0xffffffffu, s, jj);
        int   dj = __shfl_sync(0xffffffffu, d, jj);
        if (jj < cnt) {
            half2  hv = hs2[(size_t)sj * 16 + l16];
            float2 v  = __half22float2(hv);
            float* p  = &g_agg[(size_t)dj * NC + 2 * l16];
            asm volatile("red.global.add.v2.f32 [%0], {%1, %2};"
                         :: "l"(p), "f"(v.x), "f"(v.y) : "memory");
        }
    }
}

// ---------------------------------------------------------------- pooling
// node value = dinv[i] * g_agg[i][:]; batch sorted -> register accumulate,
// flush to smem only on graph boundaries.
__global__ void __launch_bounds__(256) k_pool(const int* __restrict__ batch) {
    __shared__ float sp[NG * NC];
    __shared__ float sc[NG];
    int tid = threadIdx.x;
    for (int i = tid; i < NG * NC; i += 256) sp[i] = 0.0f;
    if (tid < NG) sc[tid] = 0.0f;
    __syncthreads();

    int warp = tid >> 5, lane = tid & 31;
    int wid = blockIdx.x * 8 + warp;
    int nwarps = gridDim.x * 8;
    int per = (NN + nwarps - 1) / nwarps;
    int s0 = wid * per;
    int s1 = min(NN, s0 + per);

    float acc = 0.0f, cacc = 0.0f;
    int curg = -1;
    for (int i = s0; i < s1; i++) {
        int gidx = __ldg(&batch[i]);       // uniform broadcast load
        if (gidx != curg) {
            if (curg >= 0) {
                atomicAdd(&sp[curg * NC + lane], acc);
                if (lane == 0) atomicAdd(&sc[curg], cacc);
            }
            curg = gidx; acc = 0.0f; cacc = 0.0f;
        }
        float di = g_dinv[i];
        acc  += g_agg[(size_t)i * NC + lane] * di;
        cacc += 1.0f;
    }
    if (curg >= 0) {
        atomicAdd(&sp[curg * NC + lane], acc);
        if (lane == 0) atomicAdd(&sc[curg], cacc);
    }
    __syncthreads();

    for (int i = tid; i < NG * NC; i += 256) atomicAdd(&g_pool[i], sp[i]);
    if (tid < NG) atomicAdd(&g_cnt[tid], sc[tid]);
}

// ---------------------------------------------------------------- finalize
__global__ void k_final(const float* __restrict__ b, float* __restrict__ out) {
    int i = blockIdx.x * blockDim.x + threadIdx.x;
    if (i < NG * NC) {
        int g = i >> 5, c = i & 31;
        float cnt = g_cnt[g];
        out[i] = (cnt > 0.0f) ? (g_pool[i] / cnt + b[c]) : 0.0f;
    }
}

// ---------------------------------------------------------------- launch
extern "C" void kernel_launch(void* const* d_in, const int* in_sizes, int n_in,
                              void* d_out, int out_size) {
    const float* x     = (const float*)d_in[0];
    const float* W     = (const float*)d_in[1];
    const float* b     = (const float*)d_in[2];
    const int*   ei    = (const int*)d_in[3];
    const int*   batch = (const int*)d_in[4];
    float*       out   = (float*)d_out;

    const int* src = ei;        // edge_index[0]
    const int* dst = ei + NE;   // edge_index[1]

    k_init<<<(NN + 255) / 256, 256>>>();
    k_deg<<<(NE + 255) / 256, 256>>>(dst);
    k_dinv<<<(NN + 255) / 256, 256>>>();
    k_gemm<<<(NN + 8 * RB - 1) / (8 * RB), 256>>>(x, W);
    k_scatter<<<(NE / 32 + 7) / 8, 256>>>(src, dst);   // one warp per 32 edges
    k_pool<<<64, 256>>>(batch);
    k_final<<<(NG * NC + 255) / 256, 256>>>(b, out);
}

// round 5
// speedup vs baseline: 1.6540x; 1.0515x over previous
#include <cuda_runtime.h>
#include <cuda_fp16.h>

#define NN 100000
#define NE 3200000
#define DIMK 256
#define NC 32
#define NG 64
#define BR 256   // rows per block in gemm

// Scratch (device globals; no allocation allowed)
__device__ float  g_deg[NN];
__device__ float  g_dinv[NN];
__device__ __half g_hs_h[(size_t)NN * NC];  // h * dinv[row] in fp16 (edge gather payload)
__device__ float  g_agg[(size_t)NN * NC];   // unweighted sum of hs over in-edges (+ self hs)
__device__ float  g_pool[NG * NC];
__device__ float  g_cnt[NG];

// f32x2 packed helpers (Blackwell packed fp32)
__device__ __forceinline__ unsigned long long pk2(float a, float b) {
    unsigned long long r;
    asm("mov.b64 %0, {%1, %2};" : "=l"(r) : "f"(a), "f"(b));
    return r;
}
__device__ __forceinline__ void ffma2(unsigned long long& d, unsigned long long a,
                                      unsigned long long b) {
    asm("fma.rn.f32x2 %0, %1, %2, %0;" : "+l"(d) : "l"(a), "l"(b));
}
__device__ __forceinline__ void upk2(unsigned long long v, float& lo, float& hi) {
    asm("mov.b64 {%0, %1}, %2;" : "=f"(lo), "=f"(hi) : "l"(v));
}

// ---------------------------------------------------------------- init
__global__ void k_init() {
    int i = blockIdx.x * blockDim.x + threadIdx.x;
    if (i < NN) g_deg[i] = 1.0f;           // self-loop contributes 1
    if (i < NG * NC) g_pool[i] = 0.0f;
    if (i < NG) g_cnt[i] = 0.0f;
}

// ---------------------------------------------------------------- degree
__global__ void k_deg(const int* __restrict__ dst) {
    int i = blockIdx.x * blockDim.x + threadIdx.x;
    if (i * 4 < NE) {
        int4 d = ((const int4*)dst)[i];
        atomicAdd(&g_deg[d.x], 1.0f);
        atomicAdd(&g_deg[d.y], 1.0f);
        atomicAdd(&g_deg[d.z], 1.0f);
        atomicAdd(&g_deg[d.w], 1.0f);
    }
}

__global__ void k_dinv() {
    int i = blockIdx.x * blockDim.x + threadIdx.x;
    if (i < NN) g_dinv[i] = rsqrtf(g_deg[i]);
}

// ---------------------------------------------------------------- GEMM + self term
// Register-tiled: thread = 8 rows x 4 cols, row-paired f32x2 accumulators.
// x read directly from global (L1-dedup'd across col-group lanes, 128B-line
// reuse across k-quads). W broadcast from smem (natural [k][c] layout).
__global__ void __launch_bounds__(256, 2) k_gemm(const float* __restrict__ x,
                                                 const float* __restrict__ W) {
    __shared__ float Ws[DIMK][NC];   // 32KB

    int tid = threadIdx.x, warp = tid >> 5, lane = tid & 31;

    // Load W coalesced (2048 float4 / 256 threads = 8 each)
    for (int i = tid; i < DIMK * NC / 4; i += 256)
        ((float4*)Ws)[i] = ((const float4*)W)[i];
    __syncthreads();

    int cg = lane & 7;    // col group: cols 4cg..4cg+3
    int rg = lane >> 3;   // row group: 8 rows
    int row0 = blockIdx.x * BR + warp * 32 + rg * 8;

    const float4* xr[8];
#pragma unroll
    for (int r = 0; r < 8; r++) {
        int rr = row0 + r; if (rr >= NN) rr = NN - 1;
        xr[r] = (const float4*)(x + (size_t)rr * DIMK);
    }

    // acc[rp][c]: f32x2 over row pair (2rp, 2rp+1), col 4cg+c
    unsigned long long acc[4][4];
#pragma unroll
    for (int rp = 0; rp < 4; rp++)
#pragma unroll
        for (int c = 0; c < 4; c++) acc[rp][c] = 0ull;

#pragma unroll 4
    for (int kq = 0; kq < DIMK / 4; kq++) {
        float4 xv[8];
#pragma unroll
        for (int r = 0; r < 8; r++) xv[r] = xr[r][kq];   // dedup'd LDG.128

#pragma unroll
        for (int kk = 0; kk < 4; kk++) {
            float4 wv = *(const float4*)&Ws[4 * kq + kk][4 * cg];  // broadcast LDS
            unsigned long long wd[4];
            wd[0] = pk2(wv.x, wv.x); wd[1] = pk2(wv.y, wv.y);
            wd[2] = pk2(wv.z, wv.z); wd[3] = pk2(wv.w, wv.w);
#pragma unroll
            for (int rp = 0; rp < 4; rp++) {
                float a = (kk == 0) ? xv[2*rp].x : (kk == 1) ? xv[2*rp].y
                         : (kk == 2) ? xv[2*rp].z : xv[2*rp].w;
                float bq = (kk == 0) ? xv[2*rp+1].x : (kk == 1) ? xv[2*rp+1].y
                         : (kk == 2) ? xv[2*rp+1].z : xv[2*rp+1].w;
                unsigned long long xp = pk2(a, bq);
#pragma unroll
                for (int c = 0; c < 4; c++) ffma2(acc[rp][c], xp, wd[c]);
            }
        }
    }

    // Epilogue: hs = h*dinv; write fp16 payload + f32 self-loop seed
#pragma unroll
    for (int rp = 0; rp < 4; rp++) {
        float h0[4], h1[4];
#pragma unroll
        for (int c = 0; c < 4; c++) upk2(acc[rp][c], h0[c], h1[c]);
#pragma unroll
        for (int half_ = 0; half_ < 2; half_++) {
            int row = row0 + 2 * rp + half_;
            if (row < NN) {
                float* hv = half_ ? h1 : h0;
                float di = g_dinv[row];
                float4 hs4 = make_float4(hv[0]*di, hv[1]*di, hv[2]*di, hv[3]*di);
                *(float4*)&g_agg[(size_t)row * NC + 4 * cg] = hs4;
                half2 p0 = __floats2half2_rn(hs4.x, hs4.y);
                half2 p1 = __floats2half2_rn(hs4.z, hs4.w);
                *(uint2*)&g_hs_h[(size_t)row * NC + 4 * cg] =
                    make_uint2(*(unsigned*)&p0, *(unsigned*)&p1);
            }
        }
    }
}

// ---------------------------------------------------------------- edge scatter
// out[dst] = dinv[dst] * sum(hs[src]) -> dinv folded into pool pass.
// 8 lanes per edge: uint2 fp16 gather (8B/lane), red.v4.f32 (16B/lane).
__global__ void __launch_bounds__(256) k_scatter(const int* __restrict__ src,
                                                 const int* __restrict__ dst) {
    int gw = (blockIdx.x * blockDim.x + threadIdx.x) >> 5;
    int lane = threadIdx.x & 31;
    int base = gw * 32;               // NE % 32 == 0
    if (base >= NE) return;

    int s = src[base + lane];
    int d = dst[base + lane];

    int g  = lane >> 3;   // edge within quad
    int l8 = lane & 7;    // channel group (4 ch)
    const uint2* hs2 = (const uint2*)g_hs_h;   // 4 halves per uint2

#pragma unroll
    for (int j = 0; j < 8; j++) {
        int jj = j * 4 + g;
        int sj = __shfl_sync(0xffffffffu, s, jj);
        int dj = __shfl_sync(0xffffffffu, d, jj);
        uint2 hv = hs2[(size_t)sj * 8 + l8];
        float2 fa = __half22float2(*(half2*)&hv.x);
        float2 fb = __half22float2(*(half2*)&hv.y);
        float* p = &g_agg[(size_t)dj * NC + l8 * 4];
        asm volatile("red.global.add.v4.f32 [%0], {%1, %2, %3, %4};"
                     :: "l"(p), "f"(fa.x), "f"(fa.y), "f"(fb.x), "f"(fb.y)
                     : "memory");
    }
}

// ---------------------------------------------------------------- pooling
// node value = dinv[i] * g_agg[i][:]; batch sorted -> register accumulate,
// flush to smem only on graph boundaries.
__global__ void __launch_bounds__(256) k_pool(const int* __restrict__ batch) {
    __shared__ float sp[NG * NC];
    __shared__ float sc[NG];
    int tid = threadIdx.x;
    for (int i = tid; i < NG * NC; i += 256) sp[i] = 0.0f;
    if (tid < NG) sc[tid] = 0.0f;
    __syncthreads();

    int warp = tid >> 5, lane = tid & 31;
    int wid = blockIdx.x * 8 + warp;
    int nwarps = gridDim.x * 8;
    int per = (NN + nwarps - 1) / nwarps;
    int s0 = wid * per;
    int s1 = min(NN, s0 + per);

    float acc = 0.0f, cacc = 0.0f;
    int curg = -1;
    for (int i = s0; i < s1; i++) {
        int gidx = __ldg(&batch[i]);
        if (gidx != curg) {
            if (curg >= 0) {
                atomicAdd(&sp[curg * NC + lane], acc);
                if (lane == 0) atomicAdd(&sc[curg], cacc);
            }
            curg = gidx; acc = 0.0f; cacc = 0.0f;
        }
        float di = g_dinv[i];
        acc  += g_agg[(size_t)i * NC + lane] * di;
        cacc += 1.0f;
    }
    if (curg >= 0) {
        atomicAdd(&sp[curg * NC + lane], acc);
        if (lane == 0) atomicAdd(&sc[curg], cacc);
    }
    __syncthreads();

    for (int i = tid; i < NG * NC; i += 256) atomicAdd(&g_pool[i], sp[i]);
    if (tid < NG) atomicAdd(&g_cnt[tid], sc[tid]);
}

// ---------------------------------------------------------------- finalize
__global__ void k_final(const float* __restrict__ b, float* __restrict__ out) {
    int i = blockIdx.x * blockDim.x + threadIdx.x;
    if (i < NG * NC) {
        int g = i >> 5, c = i & 31;
        float cnt = g_cnt[g];
        out[i] = (cnt > 0.0f) ? (g_pool[i] / cnt + b[c]) : 0.0f;
    }
}

// ---------------------------------------------------------------- launch
extern "C" void kernel_launch(void* const* d_in, const int* in_sizes, int n_in,
                              void* d_out, int out_size) {
    const float* x     = (const float*)d_in[0];
    const float* W     = (const float*)d_in[1];
    const float* b     = (const float*)d_in[2];
    const int*   ei    = (const int*)d_in[3];
    const int*   batch = (const int*)d_in[4];
    float*       out   = (float*)d_out;

    const int* src = ei;        // edge_index[0]
    const int* dst = ei + NE;   // edge_index[1]

    k_init<<<(NN + 255) / 256, 256>>>();
    k_deg<<<(NE / 4 + 255) / 256, 256>>>(dst);
    k_dinv<<<(NN + 255) / 256, 256>>>();
    k_gemm<<<(NN + BR - 1) / BR, 256>>>(x, W);
    k_scatter<<<(NE / 32 + 7) / 8, 256>>>(src, dst);
    k_pool<<<64, 256>>>(batch);
    k_final<<<(NG * NC + 255) / 256, 256>>>(b, out);
}